// round 2
// baseline (speedup 1.0000x reference)
#include <cuda_runtime.h>
#include <cuda_bf16.h>
#include <cstdint>
#include <cstddef>

// ---------------------------------------------------------------------------
// ContrastiveLoss: loss = mean_i( log(sum_j exp(cos(o_i,t_j))) - cos(o_i,t_i) )
// B = 16384, D = 256, fp32 in, fp32 scalar out.
//
// compute_100 target (no tcgen05/wgmma) -> classic mma.sync bf16 pipeline.
//   prep:  normalize rows in fp32, store bf16  (cos == plain dot afterwards)
//   main:  fused 128x128x256 bf16 GEMM tiles + exp-rowsum epilogue, 1 wave
//   final: deterministic reduction of 128 CTA partials
// ---------------------------------------------------------------------------

#define NROW   16384
#define DDIM   256
#define NTILES 128
#define NCTA   128

static __device__ __align__(16) __nv_bfloat16 g_obf[NROW * DDIM]; // normalized
static __device__ __align__(16) __nv_bfloat16 g_tbf[NROW * DDIM]; // normalized
static __device__ float g_partials[NCTA];

// SMEM layout (byte offsets from dynamic smem base)
#define OFF_A    0        // 128 x 256 bf16 = 64KB, resident
#define OFF_B0   65536    // 64KB
#define OFF_B1   131072   // 64KB
#define OFF_RED  196608   // 2 x 128 floats (row partial sums)
#define OFF_DW   197632   // 8 floats
#define SMEM_DYN 197696

// ---------------------------------------------------------------------------
__device__ __forceinline__ uint32_t smem_u32(const void* p) {
    uint32_t a;
    asm("{ .reg .u64 t; cvta.to.shared.u64 t, %1; cvt.u32.u64 %0, t; }"
        : "=r"(a) : "l"(p));
    return a;
}

__device__ __forceinline__ void cp16(uint32_t dst, const void* src) {
    asm volatile("cp.async.cg.shared.global [%0], [%1], 16;"
                 :: "r"(dst), "l"(src));
}
__device__ __forceinline__ void cp_commit() {
    asm volatile("cp.async.commit_group;" ::: "memory");
}
__device__ __forceinline__ void cp_wait0() {
    asm volatile("cp.async.wait_group 0;" ::: "memory");
}

__device__ __forceinline__ void ldm4(uint32_t* r, uint32_t addr) {
    asm volatile("ldmatrix.sync.aligned.m8n8.x4.shared.b16 {%0,%1,%2,%3}, [%4];"
                 : "=r"(r[0]), "=r"(r[1]), "=r"(r[2]), "=r"(r[3]) : "r"(addr));
}

__device__ __forceinline__ void mma16816(float* d, const uint32_t* a,
                                         uint32_t b0, uint32_t b1) {
    asm volatile(
        "mma.sync.aligned.m16n8k16.row.col.f32.bf16.bf16.f32 "
        "{%0,%1,%2,%3}, {%4,%5,%6,%7}, {%8,%9}, {%0,%1,%2,%3};"
        : "+f"(d[0]), "+f"(d[1]), "+f"(d[2]), "+f"(d[3])
        : "r"(a[0]), "r"(a[1]), "r"(a[2]), "r"(a[3]), "r"(b0), "r"(b1));
}

// Async-copy one 128x256 bf16 tile into swizzled SMEM. 128 threads x 32 chunks.
// Swizzle: within a 512B row, 16B-chunk index c -> c ^ (row & 7).
__device__ __forceinline__ void tile_cp(const uint4* __restrict__ src,
                                        uint32_t dstbase, int tid) {
#pragma unroll
    for (int i = 0; i < 32; i++) {
        int c   = tid + (i << 7);
        int row = c >> 5, k16 = c & 31;
        uint32_t d = dstbase + (row << 9) + ((k16 ^ (row & 7)) << 4);
        cp16(d, src + c);
    }
}

// ---------------------------------------------------------------------------
// Kernel 1: fp32 row norms, write normalized bf16. One block per row index.
// ---------------------------------------------------------------------------
__global__ void ContrastivePrep(const float* __restrict__ O,
                                const float* __restrict__ T) {
    __shared__ float red[8];
    int r = blockIdx.x, t = threadIdx.x;          // 128 threads, 2 elems each
    float2 a = ((const float2*)O)[(size_t)r * 128 + t];
    float2 b = ((const float2*)T)[(size_t)r * 128 + t];
    float so = a.x * a.x + a.y * a.y;
    float st = b.x * b.x + b.y * b.y;
#pragma unroll
    for (int s = 16; s; s >>= 1) {
        so += __shfl_xor_sync(0xffffffffu, so, s);
        st += __shfl_xor_sync(0xffffffffu, st, s);
    }
    if ((t & 31) == 0) { red[t >> 5] = so; red[4 + (t >> 5)] = st; }
    __syncthreads();
    float io = rsqrtf(red[0] + red[1] + red[2] + red[3]);
    float it = rsqrtf(red[4] + red[5] + red[6] + red[7]);
    ((__nv_bfloat162*)g_obf)[(size_t)r * 128 + t] =
        __floats2bfloat162_rn(a.x * io, a.y * io);
    ((__nv_bfloat162*)g_tbf)[(size_t)r * 128 + t] =
        __floats2bfloat162_rn(b.x * it, b.y * it);
}

// ---------------------------------------------------------------------------
// Kernel 2: fused GEMM + exp rowsums. 128 CTAs x 128 threads (4 warps).
// Warp tile 64x64, warp grid 2x2 over the 128x128 CTA tile.
// ---------------------------------------------------------------------------
__global__ void __launch_bounds__(128, 1) ContrastiveMain() {
    extern __shared__ char smem[];
    const uint32_t sb = smem_u32(smem);
    const int tid  = threadIdx.x;
    const int lane = tid & 31, w = tid >> 5;
    const int wm = w >> 1, wn = w & 1;
    const int g  = lane >> 2, t4 = lane & 3;
    const int cta = blockIdx.x;

    // ldmatrix per-lane addressing (A-mode x4):
    // lanes 0-7 -> (rows+0, chunk+0), 8-15 -> (rows+8, chunk+0),
    // 16-23 -> (rows+0, chunk+1), 24-31 -> (rows+8, chunk+1)
    const int lrow = ((lane >> 3) & 1) * 8 + (lane & 7);
    const int lhi  = lane >> 4;
    const int x7   = lane & 7;

    uint32_t aoff[4], boff[4];
#pragma unroll
    for (int mf = 0; mf < 4; mf++)
        aoff[mf] = sb + OFF_A + (uint32_t)((wm * 64 + mf * 16 + lrow) << 9);
#pragma unroll
    for (int p = 0; p < 4; p++)
        boff[p] = (uint32_t)((wn * 64 + p * 16 + lrow) << 9);

    // Prologue: A tile (resident) + first B tile
    tile_cp((const uint4*)g_obf + (size_t)cta * 4096, sb + OFF_A, tid);
    tile_cp((const uint4*)g_tbf, sb + OFF_B0, tid);
    cp_commit();
    cp_wait0();
    __syncthreads();

    float d[4][8][4];
#pragma unroll
    for (int mf = 0; mf < 4; mf++)
#pragma unroll
        for (int nf = 0; nf < 8; nf++)
#pragma unroll
            for (int r = 0; r < 4; r++) d[mf][nf][r] = 0.f;

    float sums[8];
#pragma unroll
    for (int s = 0; s < 8; s++) sums[s] = 0.f;
    float dsum = 0.f;

    for (int j = 0; j < NTILES; j++) {
        const uint32_t bbase = sb + ((j & 1) ? OFF_B1 : OFF_B0);
        if (j + 1 < NTILES) {
            tile_cp((const uint4*)g_tbf + (size_t)(j + 1) * 4096,
                    sb + ((j & 1) ? OFF_B0 : OFF_B1), tid);
            cp_commit();
        }

        // ---- K loop: 16 ksteps of k=16 ----
#pragma unroll
        for (int ks = 0; ks < 16; ks++) {
            const uint32_t csel = (uint32_t)((((ks << 1) + lhi) ^ x7) << 4);
            uint32_t A[4][4], Bm[4][4];
#pragma unroll
            for (int mf = 0; mf < 4; mf++) ldm4(A[mf], aoff[mf] + csel);
#pragma unroll
            for (int p = 0; p < 4; p++)    ldm4(Bm[p], bbase + boff[p] + csel);
#pragma unroll
            for (int mf = 0; mf < 4; mf++)
#pragma unroll
                for (int p = 0; p < 4; p++) {
                    mma16816(d[mf][2 * p],     A[mf], Bm[p][0], Bm[p][2]);
                    mma16816(d[mf][2 * p + 1], A[mf], Bm[p][1], Bm[p][3]);
                }
        }

        // ---- epilogue: exp + per-row accumulate, capture diagonal ----
        const bool dt = (j == cta);
#pragma unroll
        for (int mf = 0; mf < 4; mf++)
#pragma unroll
            for (int h = 0; h < 2; h++) {
                float acc = 0.f;
#pragma unroll
                for (int nf = 0; nf < 8; nf++)
#pragma unroll
                    for (int rl = 0; rl < 2; rl++) {
                        float v = d[mf][nf][h * 2 + rl];
                        acc += __expf(v);
                        if (dt) {
                            int rloc = wm * 64 + mf * 16 + h * 8 + g;
                            int cloc = wn * 64 + nf * 8 + 2 * t4 + rl;
                            if (rloc == cloc) dsum += v;
                        }
                        d[mf][nf][h * 2 + rl] = 0.f;
                    }
                sums[mf * 2 + h] += acc;
            }

        if (j + 1 < NTILES) cp_wait0();
        __syncthreads();
    }

    // ---- reductions (deterministic) ----
#pragma unroll
    for (int s = 0; s < 8; s++) {
        sums[s] += __shfl_xor_sync(0xffffffffu, sums[s], 1);
        sums[s] += __shfl_xor_sync(0xffffffffu, sums[s], 2);
    }
#pragma unroll
    for (int off = 16; off; off >>= 1)
        dsum += __shfl_xor_sync(0xffffffffu, dsum, off);

    float* rp = (float*)(smem + OFF_RED);   // [2][128]
    float* dw = (float*)(smem + OFF_DW);    // [8]
    if (t4 == 0) {
#pragma unroll
        for (int s = 0; s < 8; s++) {
            int row = wm * 64 + (s >> 1) * 16 + (s & 1) * 8 + g;
            rp[wn * 128 + row] = sums[s];
        }
    }
    if (lane == 0) dw[w] = dsum;
    __syncthreads();

    float li = __logf(rp[tid] + rp[128 + tid]);   // per-row log-sum-exp (max=0 safe)
#pragma unroll
    for (int off = 16; off; off >>= 1)
        li += __shfl_xor_sync(0xffffffffu, li, off);
    if (lane == 0) dw[4 + w] = li;
    __syncthreads();

    if (tid == 0) {
        float tot = (dw[4] + dw[5] + dw[6] + dw[7])
                  - (dw[0] + dw[1] + dw[2] + dw[3]);
        g_partials[cta] = tot;
    }
}

// ---------------------------------------------------------------------------
// Kernel 3: deterministic final reduction
// ---------------------------------------------------------------------------
__global__ void ContrastiveFinal(float* out) {
    __shared__ float red[128];
    int t = threadIdx.x;
    red[t] = g_partials[t];
    __syncthreads();
#pragma unroll
    for (int s = 64; s; s >>= 1) {
        if (t < s) red[t] += red[t + s];
        __syncthreads();
    }
    if (t == 0) out[0] = red[0] / (float)NROW;
}

// ---------------------------------------------------------------------------
extern "C" void kernel_launch(void* const* d_in, const int* in_sizes, int n_in,
                              void* d_out, int out_size) {
    const float* O = (const float*)d_in[0];
    const float* T = (const float*)d_in[1];
    cudaFuncSetAttribute(ContrastiveMain,
                         cudaFuncAttributeMaxDynamicSharedMemorySize, SMEM_DYN);
    ContrastivePrep<<<NROW, 128>>>(O, T);
    ContrastiveMain<<<NCTA, 128, SMEM_DYN>>>();
    ContrastiveFinal<<<1, 128>>>((float*)d_out);
}

// round 3
// speedup vs baseline: 1.3060x; 1.3060x over previous
#include <cuda_runtime.h>
#include <cuda_bf16.h>
#include <cstdint>
#include <cstddef>

// ---------------------------------------------------------------------------
// ContrastiveLoss: loss = mean_i( log(sum_j exp(cos(o_i,t_j))) - cos(o_i,t_i) )
// B = 16384, D = 256, fp32 in, fp32 scalar out.
//
// compute_100 target (no tcgen05/wgmma) -> classic mma.sync bf16 pipeline.
//   prep:  normalize rows in fp32, store bf16  (cos == plain dot afterwards)
//   main:  fused 128x128x256 bf16 GEMM tiles + exp-rowsum epilogue, 1 wave
//          256 threads (2 warps/SMSP) so tensor/MUFU/LDSM issue overlaps
//   final: deterministic reduction of 128 CTA partials
// ---------------------------------------------------------------------------

#define NROW   16384
#define DDIM   256
#define NTILES 128
#define NCTA   128

static __device__ __align__(16) __nv_bfloat16 g_obf[NROW * DDIM]; // normalized
static __device__ __align__(16) __nv_bfloat16 g_tbf[NROW * DDIM]; // normalized
static __device__ float g_partials[NCTA];

// SMEM layout (byte offsets from dynamic smem base)
#define OFF_A    0        // 128 x 256 bf16 = 64KB, resident
#define OFF_B0   65536    // 64KB
#define OFF_B1   131072   // 64KB
#define OFF_RED  196608   // 4 x 128 floats (row partial sums per wn-warp)
#define OFF_DW   198656   // 16 floats
#define SMEM_DYN 198720

// ---------------------------------------------------------------------------
__device__ __forceinline__ uint32_t smem_u32(const void* p) {
    uint32_t a;
    asm("{ .reg .u64 t; cvta.to.shared.u64 t, %1; cvt.u32.u64 %0, t; }"
        : "=r"(a) : "l"(p));
    return a;
}

__device__ __forceinline__ void cp16(uint32_t dst, const void* src) {
    asm volatile("cp.async.cg.shared.global [%0], [%1], 16;"
                 :: "r"(dst), "l"(src));
}
__device__ __forceinline__ void cp_commit() {
    asm volatile("cp.async.commit_group;" ::: "memory");
}
__device__ __forceinline__ void cp_wait0() {
    asm volatile("cp.async.wait_group 0;" ::: "memory");
}

__device__ __forceinline__ void ldm4(uint32_t* r, uint32_t addr) {
    asm volatile("ldmatrix.sync.aligned.m8n8.x4.shared.b16 {%0,%1,%2,%3}, [%4];"
                 : "=r"(r[0]), "=r"(r[1]), "=r"(r[2]), "=r"(r[3]) : "r"(addr));
}

__device__ __forceinline__ void mma16816(float* d, const uint32_t* a,
                                         uint32_t b0, uint32_t b1) {
    asm volatile(
        "mma.sync.aligned.m16n8k16.row.col.f32.bf16.bf16.f32 "
        "{%0,%1,%2,%3}, {%4,%5,%6,%7}, {%8,%9}, {%0,%1,%2,%3};"
        : "+f"(d[0]), "+f"(d[1]), "+f"(d[2]), "+f"(d[3])
        : "r"(a[0]), "r"(a[1]), "r"(a[2]), "r"(a[3]), "r"(b0), "r"(b1));
}

// Async-copy one 128x256 bf16 tile into swizzled SMEM. 256 threads x 16 chunks.
// Swizzle: within a 512B row, 16B-chunk index c -> c ^ (row & 7).
__device__ __forceinline__ void tile_cp(const uint4* __restrict__ src,
                                        uint32_t dstbase, int tid) {
#pragma unroll
    for (int i = 0; i < 16; i++) {
        int c   = tid + (i << 8);
        int row = c >> 5, k16 = c & 31;
        uint32_t d = dstbase + (row << 9) + ((k16 ^ (row & 7)) << 4);
        cp16(d, src + c);
    }
}

// ---------------------------------------------------------------------------
// Kernel 1: fp32 row norms, write normalized bf16. One block per row index.
// ---------------------------------------------------------------------------
__global__ void ContrastivePrep(const float* __restrict__ O,
                                const float* __restrict__ T) {
    __shared__ float red[8];
    int r = blockIdx.x, t = threadIdx.x;          // 128 threads, 2 elems each
    float2 a = ((const float2*)O)[(size_t)r * 128 + t];
    float2 b = ((const float2*)T)[(size_t)r * 128 + t];
    float so = a.x * a.x + a.y * a.y;
    float st = b.x * b.x + b.y * b.y;
#pragma unroll
    for (int s = 16; s; s >>= 1) {
        so += __shfl_xor_sync(0xffffffffu, so, s);
        st += __shfl_xor_sync(0xffffffffu, st, s);
    }
    if ((t & 31) == 0) { red[t >> 5] = so; red[4 + (t >> 5)] = st; }
    __syncthreads();
    float io = rsqrtf(red[0] + red[1] + red[2] + red[3]);
    float it = rsqrtf(red[4] + red[5] + red[6] + red[7]);
    ((__nv_bfloat162*)g_obf)[(size_t)r * 128 + t] =
        __floats2bfloat162_rn(a.x * io, a.y * io);
    ((__nv_bfloat162*)g_tbf)[(size_t)r * 128 + t] =
        __floats2bfloat162_rn(b.x * it, b.y * it);
}

// ---------------------------------------------------------------------------
// Kernel 2: fused GEMM + exp rowsums. 128 CTAs x 256 threads (8 warps).
// Warp tile 64x32, warp grid 2x4 over the 128x128 CTA tile.
// ---------------------------------------------------------------------------
__global__ void __launch_bounds__(256, 1) ContrastiveMain() {
    extern __shared__ char smem[];
    const uint32_t sb = smem_u32(smem);
    const int tid  = threadIdx.x;
    const int lane = tid & 31, w = tid >> 5;
    const int wm = w >> 2, wn = w & 3;            // 2 x 4 warp grid
    const int g  = lane >> 2, t4 = lane & 3;
    const int cta = blockIdx.x;

    // ldmatrix per-lane addressing (x4 form)
    const int lrow = ((lane >> 3) & 1) * 8 + (lane & 7);
    const int lhi  = lane >> 4;
    const int x7   = lane & 7;

    uint32_t aoff[4], boff[2];
#pragma unroll
    for (int mf = 0; mf < 4; mf++)
        aoff[mf] = sb + OFF_A + (uint32_t)((wm * 64 + mf * 16 + lrow) << 9);
#pragma unroll
    for (int p = 0; p < 2; p++)
        boff[p] = (uint32_t)((wn * 32 + p * 16 + lrow) << 9);

    // Prologue: A tile (resident) + first B tile
    tile_cp((const uint4*)g_obf + (size_t)cta * 4096, sb + OFF_A, tid);
    tile_cp((const uint4*)g_tbf, sb + OFF_B0, tid);
    cp_commit();
    cp_wait0();
    __syncthreads();

    float d[4][4][4];
#pragma unroll
    for (int mf = 0; mf < 4; mf++)
#pragma unroll
        for (int nf = 0; nf < 4; nf++)
#pragma unroll
            for (int r = 0; r < 4; r++) d[mf][nf][r] = 0.f;

    float sums[8];
#pragma unroll
    for (int s = 0; s < 8; s++) sums[s] = 0.f;
    float dsum = 0.f;

    for (int j = 0; j < NTILES; j++) {
        const uint32_t bbase = sb + ((j & 1) ? OFF_B1 : OFF_B0);
        if (j + 1 < NTILES) {
            tile_cp((const uint4*)g_tbf + (size_t)(j + 1) * 4096,
                    sb + ((j & 1) ? OFF_B0 : OFF_B1), tid);
            cp_commit();
        }

        // ---- K loop: 16 ksteps of k=16 ----
#pragma unroll
        for (int ks = 0; ks < 16; ks++) {
            const uint32_t csel = (uint32_t)((((ks << 1) + lhi) ^ x7) << 4);
            uint32_t A[4][4], Bm[2][4];
#pragma unroll
            for (int mf = 0; mf < 4; mf++) ldm4(A[mf], aoff[mf] + csel);
#pragma unroll
            for (int p = 0; p < 2; p++)    ldm4(Bm[p], bbase + boff[p] + csel);
#pragma unroll
            for (int mf = 0; mf < 4; mf++)
#pragma unroll
                for (int p = 0; p < 2; p++) {
                    mma16816(d[mf][2 * p],     A[mf], Bm[p][0], Bm[p][2]);
                    mma16816(d[mf][2 * p + 1], A[mf], Bm[p][1], Bm[p][3]);
                }
        }

        // ---- epilogue: exp + per-row accumulate, capture diagonal ----
        const bool dt = (j == cta);
#pragma unroll
        for (int mf = 0; mf < 4; mf++)
#pragma unroll
            for (int h = 0; h < 2; h++) {
                float acc = 0.f;
#pragma unroll
                for (int nf = 0; nf < 4; nf++)
#pragma unroll
                    for (int rl = 0; rl < 2; rl++) {
                        float v = d[mf][nf][h * 2 + rl];
                        acc += __expf(v);
                        if (dt) {
                            int rloc = wm * 64 + mf * 16 + h * 8 + g;
                            int cloc = wn * 32 + nf * 8 + 2 * t4 + rl;
                            if (rloc == cloc) dsum += v;
                        }
                        d[mf][nf][h * 2 + rl] = 0.f;
                    }
                sums[mf * 2 + h] += acc;
            }

        if (j + 1 < NTILES) cp_wait0();
        __syncthreads();
    }

    // ---- reductions (deterministic) ----
#pragma unroll
    for (int s = 0; s < 8; s++) {
        sums[s] += __shfl_xor_sync(0xffffffffu, sums[s], 1);
        sums[s] += __shfl_xor_sync(0xffffffffu, sums[s], 2);
    }
#pragma unroll
    for (int off = 16; off; off >>= 1)
        dsum += __shfl_xor_sync(0xffffffffu, dsum, off);

    float* rp = (float*)(smem + OFF_RED);   // [4][128]: per wn-warp row sums
    float* dw = (float*)(smem + OFF_DW);    // [16]
    if (t4 == 0) {
#pragma unroll
        for (int s = 0; s < 8; s++) {
            int row = wm * 64 + (s >> 1) * 16 + (s & 1) * 8 + g;
            rp[wn * 128 + row] = sums[s];
        }
    }
    if (lane == 0) dw[w] = dsum;
    __syncthreads();

    if (tid < 128) {
        float srow = rp[tid] + rp[128 + tid] + rp[256 + tid] + rp[384 + tid];
        float li = __logf(srow);            // per-row log-sum-exp (max=0 safe)
#pragma unroll
        for (int off = 16; off; off >>= 1)
            li += __shfl_xor_sync(0xffffffffu, li, off);
        if (lane == 0) dw[8 + w] = li;
    }
    __syncthreads();

    if (tid == 0) {
        float tot = (dw[8] + dw[9] + dw[10] + dw[11])
                  - (dw[0] + dw[1] + dw[2] + dw[3]
                   + dw[4] + dw[5] + dw[6] + dw[7]);
        g_partials[cta] = tot;
    }
}

// ---------------------------------------------------------------------------
// Kernel 3: deterministic final reduction
// ---------------------------------------------------------------------------
__global__ void ContrastiveFinal(float* out) {
    __shared__ float red[128];
    int t = threadIdx.x;
    red[t] = g_partials[t];
    __syncthreads();
#pragma unroll
    for (int s = 64; s; s >>= 1) {
        if (t < s) red[t] += red[t + s];
        __syncthreads();
    }
    if (t == 0) out[0] = red[0] / (float)NROW;
}

// ---------------------------------------------------------------------------
extern "C" void kernel_launch(void* const* d_in, const int* in_sizes, int n_in,
                              void* d_out, int out_size) {
    const float* O = (const float*)d_in[0];
    const float* T = (const float*)d_in[1];
    cudaFuncSetAttribute(ContrastiveMain,
                         cudaFuncAttributeMaxDynamicSharedMemorySize, SMEM_DYN);
    ContrastivePrep<<<NROW, 128>>>(O, T);
    ContrastiveMain<<<NCTA, 256, SMEM_DYN>>>();
    ContrastiveFinal<<<1, 128>>>((float*)d_out);
}